// round 4
// baseline (speedup 1.0000x reference)
#include <cuda_runtime.h>

#define BB   16
#define TT   4096
#define FEAT 256
#define KW   5
#define NCHUNK (TT / 32)   // 128 mask words per batch

// Scratch (no allocations allowed).
__device__ float  g_weff[FEAT * KW];
__device__ float  g_bias;
__device__ float  g_p[BB * TT * KW];
__device__ float  g_alphas[BB * TT];
__device__ float  g_accb[TT * BB];       // acc BEFORE step t, transposed [t*BB+b]
__device__ unsigned g_mask[BB * NCHUNK]; // fire bitmasks
__device__ int    g_ft[BB * TT];         // fire times (dense per batch)
__device__ int2   g_seg[BB * TT];        // (prev_fire_row or -1, fire_row)
__device__ int    g_n[BB];
__device__ int    g_nofire[BB];

// ---------------------------------------------------------------------------
// Kernel 1: fold lin_w into conv_w  ->  w_eff[c,k] = sum_o lin_w[o]*conv_w[o,c,k]
// ---------------------------------------------------------------------------
__global__ void fold_kernel(const float* __restrict__ conv_w,
                            const float* __restrict__ conv_b,
                            const float* __restrict__ lin_w,
                            const float* __restrict__ lin_b) {
    int j = blockIdx.x * blockDim.x + threadIdx.x;   // j = c*KW + k
    if (j < FEAT * KW) {
        float s = 0.f;
#pragma unroll 4
        for (int o = 0; o < FEAT; ++o)
            s = fmaf(lin_w[o], conv_w[o * (FEAT * KW) + j], s);
        g_weff[j] = s;
    }
    if (blockIdx.x == 0) {
        __shared__ float sh[256];
        sh[threadIdx.x] = conv_b[threadIdx.x] * lin_w[threadIdx.x];
        __syncthreads();
        for (int ofs = 128; ofs > 0; ofs >>= 1) {
            if ((int)threadIdx.x < ofs) sh[threadIdx.x] += sh[threadIdx.x + ofs];
            __syncthreads();
        }
        if (threadIdx.x == 0) g_bias = sh[0] + lin_b[0];
    }
}

// ---------------------------------------------------------------------------
// Kernel 2: p[row][k] = dot(x[row,:], w_eff[:,k]) for k=0..4.
// ---------------------------------------------------------------------------
__global__ __launch_bounds__(256) void pk_kernel(const float* __restrict__ x) {
    int warp_global = (blockIdx.x * blockDim.x + threadIdx.x) >> 5;  // 0..8191
    int lane = threadIdx.x & 31;
    int c0 = lane * 4;

    float w[8][KW];
#pragma unroll
    for (int j = 0; j < 8; ++j) {
        int c = (j < 4) ? (c0 + j) : (c0 + 124 + j);
#pragma unroll
        for (int k = 0; k < KW; ++k) w[j][k] = g_weff[c * KW + k];
    }

    long row0 = (long)warp_global * 8;
    for (int r = 0; r < 8; ++r) {
        long row = row0 + r;
        const float4* r4 = (const float4*)(x + row * FEAT);
        float4 va = r4[lane];
        float4 vb = r4[lane + 32];
        float xs[8] = {va.x, va.y, va.z, va.w, vb.x, vb.y, vb.z, vb.w};
        float s[KW] = {0.f, 0.f, 0.f, 0.f, 0.f};
#pragma unroll
        for (int j = 0; j < 8; ++j)
#pragma unroll
            for (int k = 0; k < KW; ++k)
                s[k] = fmaf(xs[j], w[j][k], s[k]);
#pragma unroll
        for (int k = 0; k < KW; ++k)
#pragma unroll
            for (int ofs = 16; ofs > 0; ofs >>= 1)
                s[k] += __shfl_xor_sync(0xffffffffu, s[k], ofs);
        if (lane == 0) {
#pragma unroll
            for (int k = 0; k < KW; ++k) g_p[row * KW + k] = s[k];
        }
    }
}

// ---------------------------------------------------------------------------
// Kernel 3: alphas[b,t] = sigmoid( bias + sum_k p[b, t+k-2, k] )  (SAME pad)
// ---------------------------------------------------------------------------
__global__ void alpha_kernel() {
    int i = blockIdx.x * blockDim.x + threadIdx.x;   // i = b*T + t
    if (i >= BB * TT) return;
    int t = i & (TT - 1);
    float s = g_bias;
#pragma unroll
    for (int k = 0; k < KW; ++k) {
        int tt = t + k - 2;
        if (tt >= 0 && tt < TT) s += g_p[(long)(i + k - 2) * KW + k];
    }
    g_alphas[i] = 1.f / (1.f + expf(-s));
}

// ---------------------------------------------------------------------------
// Kernel 4: sequential alpha scan. 16 lanes, one per batch. Exact reference
// fp op order (fire decisions bit-identical). Critical chain forced to
// FADD(4) -> FSETP(4, pred-as-data) -> SELP(4) = 12 cyc via inline PTX.
// Per step also: 2 off-chain FADDs (a2), one coalesced STG.32 (acc_before),
// @p OR for the fire mask. Stores of (a1,a2) removed — emit recomputes them
// from acc_before with identical fp ops.
// ---------------------------------------------------------------------------
__device__ __forceinline__ void scan_step(float a, float& acc, unsigned& mask,
                                          unsigned bit) {
    float acc_new = acc + a;
    float a1 = 1.0f - acc;
    float a2 = a - a1;
    asm volatile(
        "{\n\t"
        ".reg .pred p;\n\t"
        "setp.ge.f32 p, %2, 0f3F800000;\n\t"
        "selp.f32 %0, %3, %2, p;\n\t"
        "@p or.b32 %1, %1, %4;\n\t"
        "}"
        : "=f"(acc), "+r"(mask)
        : "f"(acc_new), "f"(a2), "r"(bit));
}

__global__ __launch_bounds__(32, 1) void seq_scan_kernel() {
    int b = threadIdx.x;
    if (b >= BB) return;
    const float* ab = g_alphas + (size_t)b * TT;
    float acc = 0.f;

    float bufA[32], bufB[32];
#pragma unroll
    for (int i = 0; i < 8; ++i)
        ((float4*)bufA)[i] = ((const float4*)ab)[i];

    for (int t0 = 0; t0 < TT; t0 += 64) {
#pragma unroll
        for (int i = 0; i < 8; ++i)
            ((float4*)bufB)[i] = ((const float4*)(ab + t0 + 32))[i];

        unsigned maskA = 0u;
#pragma unroll
        for (int i = 0; i < 32; ++i) {
            g_accb[(t0 + i) * BB + b] = acc;
            scan_step(bufA[i], acc, maskA, 1u << i);
        }
        g_mask[b * NCHUNK + (t0 >> 5)] = maskA;

        if (t0 + 64 < TT) {
#pragma unroll
            for (int i = 0; i < 8; ++i)
                ((float4*)bufA)[i] = ((const float4*)(ab + t0 + 64))[i];
        }

        unsigned maskB = 0u;
#pragma unroll
        for (int i = 0; i < 32; ++i) {
            g_accb[(t0 + 32 + i) * BB + b] = acc;
            scan_step(bufB[i], acc, maskB, 1u << i);
        }
        g_mask[b * NCHUNK + (t0 >> 5) + 1] = maskB;
    }
}

// ---------------------------------------------------------------------------
// Kernel 5: compaction. One block per batch, 128 threads (one mask word each).
// ---------------------------------------------------------------------------
__global__ __launch_bounds__(128) void compact_kernel(float* __restrict__ lens,
                                                      int write_len) {
    int b = blockIdx.x;
    int t = threadIdx.x;
    __shared__ int pre[129];
    __shared__ int tmp[128];

    unsigned m = g_mask[b * NCHUNK + t];
    int cnt = __popc(m);

    tmp[t] = cnt;
    __syncthreads();
    for (int ofs = 1; ofs < 128; ofs <<= 1) {
        int v = (t >= ofs) ? tmp[t - ofs] : 0;
        __syncthreads();
        tmp[t] += v;
        __syncthreads();
    }
    pre[t + 1] = tmp[t];
    if (t == 0) pre[0] = 0;
    __syncthreads();

    int n = pre[128];
    const int wbase = b * TT;

    int rank = pre[t];
    unsigned mm = m;
    while (mm) {
        int i = __ffs(mm) - 1;
        mm &= mm - 1;
        g_ft[wbase + rank] = t * 32 + i;
        ++rank;
    }
    __syncthreads();

    if (n == 0) {
        if (t == 0) {
            g_ft[wbase] = TT - 1;
            g_seg[wbase] = make_int2(-1, TT - 1);
            g_n[b] = 1;
            g_nofire[b] = 1;
            if (write_len) lens[b] = 1.0f;
        }
        return;
    }

    for (int j = t; j < n; j += 128) {
        int s = (j == 0) ? -1 : g_ft[wbase + j - 1];
        g_seg[wbase + j] = make_int2(s, g_ft[wbase + j]);
    }
    if (t == 0) {
        g_n[b] = n;
        g_nofire[b] = 0;
        if (write_len) lens[b] = (float)n;
    }
}

// ---------------------------------------------------------------------------
// Kernel 6: fused emission + tail zero. Weights recomputed from acc_before
// with the reference's exact fp ops:
//   a1(e) = 1 - acc_before[e];   a2(s) = alpha[s] - (1 - acc_before[s]).
// ---------------------------------------------------------------------------
__global__ __launch_bounds__(FEAT) void emit_kernel(const float* __restrict__ x,
                                                    float* __restrict__ out) {
    int b = blockIdx.x;
    int d = threadIdx.x;
    int n = g_n[b];
    int nofire = g_nofire[b];
    const float* xb = x + (size_t)b * TT * FEAT;
    const float* ab = g_alphas + (size_t)b * TT;
    const int wbase = b * TT;
    float* ob = out + (size_t)b * TT * FEAT;

    for (int j = blockIdx.y; j < TT; j += gridDim.y) {
        if (j >= n) {
            ob[(size_t)j * FEAT + d] = 0.f;
            continue;
        }
        int2 se = g_seg[wbase + j];
        float accv = 0.f;
        int u0 = 0;
        if (se.x >= 0) {
            float a2 = ab[se.x] - (1.0f - g_accb[se.x * BB + b]);
            accv = a2 * xb[(size_t)se.x * FEAT + d];
            u0 = se.x + 1;
        }
        for (int u = u0; u < se.y; ++u)
            accv = fmaf(ab[u], xb[(size_t)u * FEAT + d], accv);
        float we = nofire ? ab[se.y] : (1.0f - g_accb[se.y * BB + b]);
        accv = fmaf(we, xb[(size_t)se.y * FEAT + d], accv);
        ob[(size_t)j * FEAT + d] = accv;
    }
}

// ---------------------------------------------------------------------------
extern "C" void kernel_launch(void* const* d_in, const int* in_sizes, int n_in,
                              void* d_out, int out_size) {
    const float* x      = (const float*)d_in[0];
    const float* conv_w = (const float*)d_in[1];
    const float* conv_b = (const float*)d_in[2];
    const float* lin_w  = (const float*)d_in[3];
    const float* lin_b  = (const float*)d_in[4];
    float* out = (float*)d_out;

    const size_t dense = (size_t)BB * TT * FEAT;
    if ((size_t)out_size > dense)
        cudaMemsetAsync(out + dense, 0, ((size_t)out_size - dense) * sizeof(float), 0);

    fold_kernel<<<5, 256>>>(conv_w, conv_b, lin_w, lin_b);
    pk_kernel<<<1024, 256>>>(x);
    alpha_kernel<<<(BB * TT + 255) / 256, 256>>>();

    seq_scan_kernel<<<1, 32>>>();

    int write_len = (out_size >= BB * TT * FEAT + BB) ? 1 : 0;
    float* lens = out + dense;
    compact_kernel<<<BB, 128>>>(lens, write_len);

    emit_kernel<<<dim3(BB, 256), FEAT>>>(x, out);
}

// round 5
// speedup vs baseline: 1.0438x; 1.0438x over previous
#include <cuda_runtime.h>

#define BB   16
#define TT   4096
#define FEAT 256
#define KW   5
#define NCHUNK (TT / 32)   // 128 mask words per batch
#define CH   64            // seq_scan chunk (steps)

// Scratch (no allocations allowed).
__device__ float  g_weff[FEAT * KW];
__device__ float  g_bias;
__device__ float  g_p[BB * TT * KW];
__device__ float  g_alphas[BB * TT];     // [b][t] for emit/compact
__device__ float  g_alphasT[TT * BB];    // [t][b] for seq_scan (coalesced)
__device__ float4 g_accq4[(TT / 4) * BB]; // acc BEFORE step, 4 steps per float4: [(t>>2)*16+b]
__device__ int    g_ft[BB * TT];
__device__ int2   g_seg[BB * TT];
__device__ int    g_n[BB];
__device__ int    g_nofire[BB];

#define ACCB(t, b) (((const float*)g_accq4)[(((t) >> 2) * BB + (b)) * 4 + ((t) & 3)])

// ---------------------------------------------------------------------------
// Kernel 1: fold lin_w into conv_w  ->  w_eff[c,k] = sum_o lin_w[o]*conv_w[o,c,k]
// ---------------------------------------------------------------------------
__global__ void fold_kernel(const float* __restrict__ conv_w,
                            const float* __restrict__ conv_b,
                            const float* __restrict__ lin_w,
                            const float* __restrict__ lin_b) {
    int j = blockIdx.x * blockDim.x + threadIdx.x;   // j = c*KW + k
    if (j < FEAT * KW) {
        float s = 0.f;
#pragma unroll 4
        for (int o = 0; o < FEAT; ++o)
            s = fmaf(lin_w[o], conv_w[o * (FEAT * KW) + j], s);
        g_weff[j] = s;
    }
    if (blockIdx.x == 0) {
        __shared__ float sh[256];
        sh[threadIdx.x] = conv_b[threadIdx.x] * lin_w[threadIdx.x];
        __syncthreads();
        for (int ofs = 128; ofs > 0; ofs >>= 1) {
            if ((int)threadIdx.x < ofs) sh[threadIdx.x] += sh[threadIdx.x + ofs];
            __syncthreads();
        }
        if (threadIdx.x == 0) g_bias = sh[0] + lin_b[0];
    }
}

// ---------------------------------------------------------------------------
// Kernel 2: p[row][k] = dot(x[row,:], w_eff[:,k]) for k=0..4.
// ---------------------------------------------------------------------------
__global__ __launch_bounds__(256) void pk_kernel(const float* __restrict__ x) {
    int warp_global = (blockIdx.x * blockDim.x + threadIdx.x) >> 5;  // 0..8191
    int lane = threadIdx.x & 31;
    int c0 = lane * 4;

    float w[8][KW];
#pragma unroll
    for (int j = 0; j < 8; ++j) {
        int c = (j < 4) ? (c0 + j) : (c0 + 124 + j);
#pragma unroll
        for (int k = 0; k < KW; ++k) w[j][k] = g_weff[c * KW + k];
    }

    long row0 = (long)warp_global * 8;
    for (int r = 0; r < 8; ++r) {
        long row = row0 + r;
        const float4* r4 = (const float4*)(x + row * FEAT);
        float4 va = r4[lane];
        float4 vb = r4[lane + 32];
        float xs[8] = {va.x, va.y, va.z, va.w, vb.x, vb.y, vb.z, vb.w};
        float s[KW] = {0.f, 0.f, 0.f, 0.f, 0.f};
#pragma unroll
        for (int j = 0; j < 8; ++j)
#pragma unroll
            for (int k = 0; k < KW; ++k)
                s[k] = fmaf(xs[j], w[j][k], s[k]);
#pragma unroll
        for (int k = 0; k < KW; ++k)
#pragma unroll
            for (int ofs = 16; ofs > 0; ofs >>= 1)
                s[k] += __shfl_xor_sync(0xffffffffu, s[k], ofs);
        if (lane == 0) {
#pragma unroll
            for (int k = 0; k < KW; ++k) g_p[row * KW + k] = s[k];
        }
    }
}

// ---------------------------------------------------------------------------
// Kernel 3: alphas[b,t] = sigmoid( bias + sum_k p[b, t+k-2, k] )  (SAME pad)
// Writes both [b][t] and transposed [t][b] copies.
// ---------------------------------------------------------------------------
__global__ void alpha_kernel() {
    int i = blockIdx.x * blockDim.x + threadIdx.x;   // i = b*T + t
    if (i >= BB * TT) return;
    int t = i & (TT - 1);
    int b = i >> 12;
    float s = g_bias;
#pragma unroll
    for (int k = 0; k < KW; ++k) {
        int tt = t + k - 2;
        if (tt >= 0 && tt < TT) s += g_p[(long)(i + k - 2) * KW + k];
    }
    float v = 1.f / (1.f + expf(-s));
    g_alphas[i] = v;
    g_alphasT[t * BB + b] = v;
}

// ---------------------------------------------------------------------------
// Kernel 4: sequential alpha scan. 16 active lanes (one per batch), all 32
// lanes cooperate on staging. Chunks of 64 steps double-buffered in smem:
// LDG(next chunk) issued at chunk top (consumed by STS at chunk end — cannot
// be sunk), current chunk read via conflict-free LDS with one-subchunk
// lookahead. Loop body is the bare 12-cyc FADD->FSETP->FSEL chain; acc_before
// written as one STG.128 per 4 steps; NO fire bookkeeping (compact recomputes
// it with identical fp ops).
// ---------------------------------------------------------------------------
__global__ __launch_bounds__(32, 1) void seq_scan_kernel() {
    __shared__ float sa[2][CH * BB];          // 2 x 4KB
    const int lane = threadIdx.x;
    const int b = lane & 15;

    const float4* src = (const float4*)g_alphasT;   // 64 bytes per step-row

    // preload chunk 0
    {
        float4 v[8];
#pragma unroll
        for (int i = 0; i < 8; ++i) v[i] = src[lane + 32 * i];
#pragma unroll
        for (int i = 0; i < 8; ++i) ((float4*)sa[0])[lane + 32 * i] = v[i];
    }
    __syncwarp();

    float acc = 0.f;
    int buf = 0;
    float4* accq = g_accq4;

    for (int c = 0; c < TT / CH; ++c) {
        // prefetch next chunk from GMEM into registers
        float4 pf[8];
        if (c + 1 < TT / CH) {
            const float4* s2 = src + (c + 1) * (CH * BB / 4);
#pragma unroll
            for (int i = 0; i < 8; ++i) pf[i] = s2[lane + 32 * i];
        }

        if (lane < 16) {
            const float* s = sa[buf] + b;
            float cur[16], nxt[16];
#pragma unroll
            for (int j = 0; j < 16; ++j) cur[j] = s[j * BB];
#pragma unroll
            for (int sub = 0; sub < CH / 16; ++sub) {
                if (sub + 1 < CH / 16) {
#pragma unroll
                    for (int j = 0; j < 16; ++j)
                        nxt[j] = s[(sub * 16 + 16 + j) * BB];
                }
                int qbase = (c * CH + sub * 16) >> 2;   // float4 group index
#pragma unroll
                for (int q = 0; q < 4; ++q) {
                    float4 av;
#pragma unroll
                    for (int j = 0; j < 4; ++j) {
                        float a = cur[q * 4 + j];
                        ((float*)&av)[j] = acc;
                        float acc_new = acc + a;
                        float a1 = 1.0f - acc;
                        float a2 = a - a1;
                        acc = (acc_new >= 1.0f) ? a2 : acc_new;
                    }
                    accq[(qbase + q) * BB + b] = av;
                }
#pragma unroll
                for (int j = 0; j < 16; ++j) cur[j] = nxt[j];
            }
        }

        if (c + 1 < TT / CH) {
            buf ^= 1;
            __syncwarp();
#pragma unroll
            for (int i = 0; i < 8; ++i)
                ((float4*)sa[buf])[lane + 32 * i] = pf[i];
            __syncwarp();
        }
    }
}

// ---------------------------------------------------------------------------
// Kernel 5: compaction. Recomputes fire = (acc_before + alpha >= 1) with the
// exact fp32 op the scan used (identical operands -> identical result), then
// prefix + scatter to build the segment table.
// ---------------------------------------------------------------------------
__global__ __launch_bounds__(128) void compact_kernel(float* __restrict__ lens,
                                                      int write_len) {
    int b = blockIdx.x;
    int t = threadIdx.x;
    __shared__ int pre[129];
    __shared__ int tmp[128];

    // rebuild this thread's 32-step fire mask
    unsigned m = 0u;
    {
        int base = t * 32;
        const float* ab = g_alphas + (size_t)b * TT + base;
        const float4* aq = g_accq4 + (base >> 2) * BB + b;
#pragma unroll
        for (int qq = 0; qq < 8; ++qq) {
            float4 v = aq[qq * BB];
            float accs[4] = {v.x, v.y, v.z, v.w};
#pragma unroll
            for (int j = 0; j < 4; ++j) {
                int i = qq * 4 + j;
                if (accs[j] + ab[i] >= 1.0f) m |= (1u << i);
            }
        }
    }
    int cnt = __popc(m);

    tmp[t] = cnt;
    __syncthreads();
    for (int ofs = 1; ofs < 128; ofs <<= 1) {
        int v = (t >= ofs) ? tmp[t - ofs] : 0;
        __syncthreads();
        tmp[t] += v;
        __syncthreads();
    }
    pre[t + 1] = tmp[t];
    if (t == 0) pre[0] = 0;
    __syncthreads();

    int n = pre[128];
    const int wbase = b * TT;

    int rank = pre[t];
    unsigned mm = m;
    while (mm) {
        int i = __ffs(mm) - 1;
        mm &= mm - 1;
        g_ft[wbase + rank] = t * 32 + i;
        ++rank;
    }
    __syncthreads();

    if (n == 0) {
        if (t == 0) {
            g_ft[wbase] = TT - 1;
            g_seg[wbase] = make_int2(-1, TT - 1);
            g_n[b] = 1;
            g_nofire[b] = 1;
            if (write_len) lens[b] = 1.0f;
        }
        return;
    }

    for (int j = t; j < n; j += 128) {
        int s = (j == 0) ? -1 : g_ft[wbase + j - 1];
        g_seg[wbase + j] = make_int2(s, g_ft[wbase + j]);
    }
    if (t == 0) {
        g_n[b] = n;
        g_nofire[b] = 0;
        if (write_len) lens[b] = (float)n;
    }
}

// ---------------------------------------------------------------------------
// Kernel 6: fused emission + tail zero. Weights recomputed from acc_before
// with the reference's exact fp ops:
//   a1(e) = 1 - acc_before[e];   a2(s) = alpha[s] - (1 - acc_before[s]).
// ---------------------------------------------------------------------------
__global__ __launch_bounds__(FEAT) void emit_kernel(const float* __restrict__ x,
                                                    float* __restrict__ out) {
    int b = blockIdx.x;
    int d = threadIdx.x;
    int n = g_n[b];
    int nofire = g_nofire[b];
    const float* xb = x + (size_t)b * TT * FEAT;
    const float* ab = g_alphas + (size_t)b * TT;
    const int wbase = b * TT;
    float* ob = out + (size_t)b * TT * FEAT;

    for (int j = blockIdx.y; j < TT; j += gridDim.y) {
        if (j >= n) {
            ob[(size_t)j * FEAT + d] = 0.f;
            continue;
        }
        int2 se = g_seg[wbase + j];
        float accv = 0.f;
        int u0 = 0;
        if (se.x >= 0) {
            float a2 = ab[se.x] - (1.0f - ACCB(se.x, b));
            accv = a2 * xb[(size_t)se.x * FEAT + d];
            u0 = se.x + 1;
        }
        for (int u = u0; u < se.y; ++u)
            accv = fmaf(ab[u], xb[(size_t)u * FEAT + d], accv);
        float we = nofire ? ab[se.y] : (1.0f - ACCB(se.y, b));
        accv = fmaf(we, xb[(size_t)se.y * FEAT + d], accv);
        ob[(size_t)j * FEAT + d] = accv;
    }
}

// ---------------------------------------------------------------------------
extern "C" void kernel_launch(void* const* d_in, const int* in_sizes, int n_in,
                              void* d_out, int out_size) {
    const float* x      = (const float*)d_in[0];
    const float* conv_w = (const float*)d_in[1];
    const float* conv_b = (const float*)d_in[2];
    const float* lin_w  = (const float*)d_in[3];
    const float* lin_b  = (const float*)d_in[4];
    float* out = (float*)d_out;

    const size_t dense = (size_t)BB * TT * FEAT;
    if ((size_t)out_size > dense)
        cudaMemsetAsync(out + dense, 0, ((size_t)out_size - dense) * sizeof(float), 0);

    fold_kernel<<<5, 256>>>(conv_w, conv_b, lin_w, lin_b);
    pk_kernel<<<1024, 256>>>(x);
    alpha_kernel<<<(BB * TT + 255) / 256, 256>>>();

    seq_scan_kernel<<<1, 32>>>();

    int write_len = (out_size >= BB * TT * FEAT + BB) ? 1 : 0;
    float* lens = out + dense;
    compact_kernel<<<BB, 128>>>(lens, write_len);

    emit_kernel<<<dim3(BB, 256), FEAT>>>(x, out);
}